// round 1
// baseline (speedup 1.0000x reference)
#include <cuda_runtime.h>

#define PLEN 2048
#define BATCH 2
#define NH 8
#define DH 64
#define DM 512

// Scratch (allocation-free: __device__ globals)
__device__ float g_q[BATCH * PLEN * DM];
__device__ float g_k[BATCH * PLEN * DM];
__device__ float g_v[BATCH * PLEN * DM];
__device__ float g_oh[BATCH * PLEN * DM];
__device__ float g_S[(size_t)BATCH * NH * PLEN * PLEN];  // 268 MB: scores, then post-mix attn (in place)

// ---------------------------------------------------------------------------
// Generic 64x64 tile GEMM (fp32, 256 threads, 4x4 per thread, BK=16)
// TB=false: C = A[MxK] * B[KxN]   (both row-major)
// TB=true : C = A[MxK] * B[NxK]^T (both row-major, K contiguous)
// ---------------------------------------------------------------------------
template <bool TB>
__device__ __forceinline__ void gemm64_tile(
    const float* __restrict__ A, int lda,
    const float* __restrict__ B, int ldb,
    float* __restrict__ C, int ldc,
    int K, float alpha, int m0, int n0)
{
    __shared__ float As[16][68];
    __shared__ float Bs[16][68];

    const int tid = threadIdx.x;       // 0..255
    const int tx = tid & 15;           // n micro-tile
    const int ty = tid >> 4;           // m micro-tile
    const int lr = tid >> 2;           // 0..63  (row for transposed loads)
    const int lc = (tid & 3) << 2;     // 0,4,8,12 (k offset for transposed loads)

    float acc[4][4];
#pragma unroll
    for (int i = 0; i < 4; i++)
#pragma unroll
        for (int j = 0; j < 4; j++) acc[i][j] = 0.f;

    for (int k0 = 0; k0 < K; k0 += 16) {
        // global loads for this chunk
        float4 av = *(const float4*)(A + (size_t)(m0 + lr) * lda + k0 + lc);
        float4 bv;
        if (TB) {
            bv = *(const float4*)(B + (size_t)(n0 + lr) * ldb + k0 + lc);
        } else {
            bv = *(const float4*)(B + (size_t)(k0 + ty) * ldb + n0 + (tx << 2));
        }
        __syncthreads();  // previous compute done before overwriting smem
        As[lc + 0][lr] = av.x;
        As[lc + 1][lr] = av.y;
        As[lc + 2][lr] = av.z;
        As[lc + 3][lr] = av.w;
        if (TB) {
            Bs[lc + 0][lr] = bv.x;
            Bs[lc + 1][lr] = bv.y;
            Bs[lc + 2][lr] = bv.z;
            Bs[lc + 3][lr] = bv.w;
        } else {
            *(float4*)&Bs[ty][tx << 2] = bv;
        }
        __syncthreads();
#pragma unroll
        for (int kk = 0; kk < 16; kk++) {
            float4 a4 = *(const float4*)&As[kk][ty << 2];
            float4 b4 = *(const float4*)&Bs[kk][tx << 2];
            float a_[4] = {a4.x, a4.y, a4.z, a4.w};
            float b_[4] = {b4.x, b4.y, b4.z, b4.w};
#pragma unroll
            for (int i = 0; i < 4; i++)
#pragma unroll
                for (int j = 0; j < 4; j++) acc[i][j] += a_[i] * b_[j];
        }
    }

#pragma unroll
    for (int i = 0; i < 4; i++) {
        float* Crow = C + (size_t)(m0 + (ty << 2) + i) * ldc + n0 + (tx << 2);
#pragma unroll
        for (int j = 0; j < 4; j++) Crow[j] = acc[i][j] * alpha;
    }
}

// ---------------------------------------------------------------------------
// Stage 1: Q/K/V projections.  grid (8, 64, 3), 256 thr
// ---------------------------------------------------------------------------
__global__ __launch_bounds__(256) void k_qkv(
    const float* __restrict__ x,
    const float* __restrict__ Wq,
    const float* __restrict__ Wk,
    const float* __restrict__ Wv)
{
    int nt = blockIdx.x, mt = blockIdx.y, which = blockIdx.z;
    const float* W = (which == 0) ? Wq : (which == 1) ? Wk : Wv;
    float* O = (which == 0) ? g_q : (which == 1) ? g_k : g_v;
    float alpha = (which == 0) ? 0.125f : 1.0f;  // q /= sqrt(64)
    gemm64_tile<false>(x, DM, W, DM, O, DM, DM, alpha, mt * 64, nt * 64);
}

// ---------------------------------------------------------------------------
// Stage 2: raw scores S[b,h] = q_h @ k_h^T.  grid (32, 32, 16), 256 thr
// ---------------------------------------------------------------------------
__global__ __launch_bounds__(256) void k_scores()
{
    int jt = blockIdx.x, it = blockIdx.y, z = blockIdx.z;
    int b = z >> 3, h = z & 7;
    const float* A = g_q + (size_t)b * PLEN * DM + h * DH;
    const float* B = g_k + (size_t)b * PLEN * DM + h * DH;
    float* C = g_S + (size_t)z * PLEN * PLEN;
    gemm64_tile<true>(A, DM, B, DM, C, PLEN, DH, 1.0f, it * 64, jt * 64);
}

// ---------------------------------------------------------------------------
// Stage 3: head-mix (W1) -> softmax -> head-mix (W2, /l folded), in place.
// One CTA per (b, i): reads S[b,:,i,:], writes A3[b,:,i,:].
// grid (2048, 2), 512 thr, 64 KB dynamic smem
// ---------------------------------------------------------------------------
__device__ __forceinline__ float block_reduce_max(float v, float* red)
{
#pragma unroll
    for (int o = 16; o; o >>= 1) v = fmaxf(v, __shfl_xor_sync(0xffffffffu, v, o));
    int w = threadIdx.x >> 5;
    if ((threadIdx.x & 31) == 0) red[w] = v;
    __syncthreads();
    if (threadIdx.x < 16) {
        v = red[threadIdx.x];
#pragma unroll
        for (int o = 8; o; o >>= 1) v = fmaxf(v, __shfl_xor_sync(0xffffu, v, o));
        if (threadIdx.x == 0) red[0] = v;
    }
    __syncthreads();
    v = red[0];
    __syncthreads();
    return v;
}

__device__ __forceinline__ float block_reduce_sum(float v, float* red)
{
#pragma unroll
    for (int o = 16; o; o >>= 1) v += __shfl_xor_sync(0xffffffffu, v, o);
    int w = threadIdx.x >> 5;
    if ((threadIdx.x & 31) == 0) red[w] = v;
    __syncthreads();
    if (threadIdx.x < 16) {
        v = red[threadIdx.x];
#pragma unroll
        for (int o = 8; o; o >>= 1) v += __shfl_xor_sync(0xffffu, v, o);
        if (threadIdx.x == 0) red[0] = v;
    }
    __syncthreads();
    v = red[0];
    __syncthreads();
    return v;
}

__global__ __launch_bounds__(512) void k_mix_softmax(
    const float* __restrict__ W1, const float* __restrict__ W2)
{
    extern __shared__ float smix[];  // [8][2048]
    __shared__ float red[16];
    __shared__ float w1s[64];
    __shared__ float lstat[8];
    __shared__ float w2l[64];

    const int tid = threadIdx.x;  // 512
    const int i = blockIdx.x;
    const int b = blockIdx.y;

    if (tid < 64) w1s[tid] = W1[tid];
    __syncthreads();

    float* Srow = g_S + (size_t)b * NH * PLEN * PLEN + (size_t)i * PLEN;  // + h*P*P

    // mix1: smix[g][j] = sum_h W1[h,g] * S[b,h,i,j]
#pragma unroll
    for (int j0 = 0; j0 < PLEN; j0 += 512) {
        int j = j0 + tid;
        float r[8];
#pragma unroll
        for (int h = 0; h < 8; h++) r[h] = Srow[(size_t)h * PLEN * PLEN + j];
#pragma unroll
        for (int g = 0; g < 8; g++) {
            float a = 0.f;
#pragma unroll
            for (int h = 0; h < 8; h++) a += w1s[h * 8 + g] * r[h];
            smix[g * PLEN + j] = a;
        }
    }
    __syncthreads();

    // softmax per g (exp in place; keep l)
    for (int g = 0; g < 8; g++) {
        float m = -1e30f;
        for (int j = tid; j < PLEN; j += 512) m = fmaxf(m, smix[g * PLEN + j]);
        m = block_reduce_max(m, red);
        float l = 0.f;
        for (int j = tid; j < PLEN; j += 512) {
            float e = __expf(smix[g * PLEN + j] - m);
            smix[g * PLEN + j] = e;
            l += e;
        }
        l = block_reduce_sum(l, red);
        if (tid == 0) lstat[g] = l;
        __syncthreads();
    }

    // w2l[g][g'] = W2[g,g'] / l_g
    if (tid < 64) w2l[tid] = W2[tid] / lstat[tid >> 3];
    __syncthreads();

    // mix2 + writeback (in place over the same rows)
#pragma unroll
    for (int j0 = 0; j0 < PLEN; j0 += 512) {
        int j = j0 + tid;
        float e[8];
#pragma unroll
        for (int g = 0; g < 8; g++) e[g] = smix[g * PLEN + j];
#pragma unroll
        for (int gp = 0; gp < 8; gp++) {
            float a = 0.f;
#pragma unroll
            for (int g = 0; g < 8; g++) a += w2l[g * 8 + gp] * e[g];
            Srow[(size_t)gp * PLEN * PLEN + j] = a;
        }
    }
}

// ---------------------------------------------------------------------------
// Stage 4: out_heads[b,g] = A3[b,g] @ v[b,:,g*64:...]. grid (32, 1, 16), 256 thr
// ---------------------------------------------------------------------------
__global__ __launch_bounds__(256) void k_pv()
{
    int it = blockIdx.x, z = blockIdx.z;
    int b = z >> 3, g = z & 7;
    const float* A = g_S + (size_t)z * PLEN * PLEN;
    const float* B = g_v + (size_t)b * PLEN * DM + g * DH;
    float* C = g_oh + (size_t)b * PLEN * DM + g * DH;
    gemm64_tile<false>(A, PLEN, B, DM, C, DM, PLEN, 1.0f, it * 64, 0);
}

// ---------------------------------------------------------------------------
// Stage 5: out = out_heads @ Wproj. grid (8, 64), 256 thr
// ---------------------------------------------------------------------------
__global__ __launch_bounds__(256) void k_proj(const float* __restrict__ Wp,
                                              float* __restrict__ out)
{
    gemm64_tile<false>(g_oh, DM, Wp, DM, out, DM, DM, 1.0f,
                       blockIdx.y * 64, blockIdx.x * 64);
}

// ---------------------------------------------------------------------------
extern "C" void kernel_launch(void* const* d_in, const int* in_sizes, int n_in,
                              void* d_out, int out_size)
{
    const float* x     = (const float*)d_in[0];
    const float* Wq    = (const float*)d_in[1];
    const float* Wk    = (const float*)d_in[2];
    const float* Wv    = (const float*)d_in[3];
    const float* W1    = (const float*)d_in[4];
    const float* W2    = (const float*)d_in[5];
    const float* Wproj = (const float*)d_in[6];
    float* out = (float*)d_out;

    cudaFuncSetAttribute(k_mix_softmax,
                         cudaFuncAttributeMaxDynamicSharedMemorySize, 65536);

    k_qkv<<<dim3(8, 64, 3), 256>>>(x, Wq, Wk, Wv);
    k_scores<<<dim3(32, 32, 16), 256>>>();
    k_mix_softmax<<<dim3(2048, 2, 1), 512, 65536>>>(W1, W2);
    k_pv<<<dim3(32, 1, 16), 256>>>();
    k_proj<<<dim3(8, 64), 256>>>(Wproj, out);
}